// round 11
// baseline (speedup 1.0000x reference)
#include <cuda_runtime.h>
#include <stdint.h>

// Fixed-shape problem constants
#define HH 352
#define WW 1216
#define PP 65536
#define CC 64
#define BB 2
#define HW (HH * WW)            // 428032
#define NPIX (BB * HW)          // 856064
#define MAXC 8                  // per-pixel candidate capacity (= reference K)

// Scratch (__device__ globals: allocation-free).
// INVARIANT: d_count == 0 at entry of every kernel_launch call.
//  - first call: BSS zero-initialization
//  - later calls: trailing reset_kernel of the previous call
// Every call performs identical work -> graph-replay deterministic.
__device__ int    d_count[NPIX];
__device__ uint2  d_cand[NPIX * MAXC];          // {pid, bitcast(weight)}
__device__ float  d_featsT[BB * PP * CC];       // src transposed to [B*P, C]

#define T_TILES (PP / 32 * (CC / 32) * BB)      // 8192 transpose tiles
#define B_BLOCKS ((BB * PP) / 256)              // 512 build blocks
#define R_BLOCKS (NPIX / 4 / 256)               // 836 reset blocks

// ------------------------------------------------- transpose + build (fused)
// Disjoint data: transpose src->featsT, build pts->count/cand. Their blocks
// run concurrently in one grid (build hides inside the memory-bound tail).
__global__ void __launch_bounds__(256)
prep_kernel(const float* __restrict__ src, const float* __restrict__ pts) {
    int bid = blockIdx.x;
    int tid = threadIdx.x;

    if (bid < T_TILES) {
        // src [B, C, P] -> d_featsT [B*P, C], 32x32 smem tile
        __shared__ float tile[32][33];
        int pb   = bid & (PP / 32 - 1);
        int rest = bid >> 11;
        int cb   = rest & 1;
        int b    = rest >> 1;
        int tx = tid & 31, ty = tid >> 5;
        int pbase = pb * 32, cbase = cb * 32;
        const float* sb = src + (size_t)b * CC * PP;
        #pragma unroll
        for (int j = 0; j < 4; j++) {
            int c = cbase + ty + j * 8;
            tile[ty + j * 8][tx] = sb[(size_t)c * PP + pbase + tx];
        }
        __syncthreads();
        float* ob = d_featsT + ((size_t)b * PP) * CC;
        #pragma unroll
        for (int j = 0; j < 4; j++) {
            int p = pbase + ty + j * 8;
            ob[(size_t)p * CC + cbase + tx] = tile[tx][ty + j * 8];
        }
    } else {
        // ---- build candidate lists ----
        // r = 3/1216 NDC. Row pitch 2/352 > 2r -> only row i0 qualifies.
        // Col pitch 2/1216, 2r spans <=3 centers -> only j0-1..j0+1.
        int t = (bid - T_TILES) * 256 + tid;    // point index
        int b = t >> 16;

        float x = pts[3 * t + 0];
        float y = pts[3 * t + 1];
        float z = pts[3 * t + 2];

        const float r2     = (3.0f / 1216.0f) * (3.0f / 1216.0f);
        const float inv_r2 = 1216.0f * 1216.0f / 9.0f;

        int i0 = (int)floorf((y + 1.0f) * 0.5f * (float)HH);
        int j0 = (int)floorf((x + 1.0f) * 0.5f * (float)WW);

        if (!(z > 0.0f) || i0 < 0 || i0 >= HH) return;

        float yc  = ((float)i0 + 0.5f) * (2.0f / (float)HH) - 1.0f;
        float fy2 = (y - yc) * (y - yc);

        #pragma unroll
        for (int dxi = -1; dxi <= 1; dxi++) {
            int jj = j0 + dxi;
            if (jj < 0 || jj >= WW) continue;
            float xc = ((float)jj + 0.5f) * (2.0f / (float)WW) - 1.0f;
            float fx = x - xc;
            float d2 = fx * fx + fy2;
            if (d2 < r2) {
                float alpha = 1.0f - sqrtf(fmaxf(d2 * inv_r2, 0.001f));
                int pix = (b * HH + i0) * WW + jj;
                int idx = atomicAdd(&d_count[pix], 1);
                if (idx < MAXC)
                    d_cand[pix * MAXC + idx] = make_uint2((unsigned)t, __float_as_uint(alpha));
            }
        }
    }
}

// ------------------------------------------------- gather
// Thread = one pixel x 32 channels (half the channels; blockIdx.y selects
// the half). Shorter serial chain + 2x blocks + 100% occupancy target.
__global__ void __launch_bounds__(256, 8)
gather_kernel(float* __restrict__ out) {
    int pix  = blockIdx.x * 256 + threadIdx.x;
    int half = blockIdx.y;                       // 0 or 1 -> channels 32*half..

    int n = d_count[pix];
    n = n < MAXC ? n : MAXC;

    // Hoist candidate entries into registers.
    const uint4* cb4 = (const uint4*)(d_cand + (size_t)pix * MAXC);
    uint4 e01 = make_uint4(0,0,0,0), e23 = e01, e45 = e01, e67 = e01;
    if (n > 0) e01 = __ldg(&cb4[0]);
    if (n > 2) e23 = __ldg(&cb4[1]);
    if (n > 4) e45 = __ldg(&cb4[2]);
    if (n > 6) e67 = __ldg(&cb4[3]);

    unsigned pid[MAXC];
    float    wgt[MAXC];
    pid[0] = e01.x; wgt[0] = __uint_as_float(e01.y);
    pid[1] = e01.z; wgt[1] = __uint_as_float(e01.w);
    pid[2] = e23.x; wgt[2] = __uint_as_float(e23.y);
    pid[3] = e23.z; wgt[3] = __uint_as_float(e23.w);
    pid[4] = e45.x; wgt[4] = __uint_as_float(e45.y);
    pid[5] = e45.z; wgt[5] = __uint_as_float(e45.w);
    pid[6] = e67.x; wgt[6] = __uint_as_float(e67.y);
    pid[7] = e67.z; wgt[7] = __uint_as_float(e67.w);

    int b   = pix / HW;
    int loc = pix - b * HW;
    float* ob = out + (size_t)b * CC * HW + (size_t)(half * 32) * HW + loc;

    #pragma unroll
    for (int g = 0; g < 4; g++) {
        float4 accA = make_float4(0.f, 0.f, 0.f, 0.f);
        float4 accB = make_float4(0.f, 0.f, 0.f, 0.f);
        #pragma unroll
        for (int i = 0; i < MAXC; i++) {
            if (i < n) {
                const float4* fp = (const float4*)
                    (d_featsT + (size_t)pid[i] * CC + half * 32 + g * 8);
                float4 a = __ldg(fp);
                float4 c = __ldg(fp + 1);
                float w = wgt[i];
                accA.x += w * a.x; accA.y += w * a.y; accA.z += w * a.z; accA.w += w * a.w;
                accB.x += w * c.x; accB.y += w * c.y; accB.z += w * c.z; accB.w += w * c.w;
            }
        }
        float* oc = ob + (size_t)(g * 8) * HW;
        __stcs(oc + 0 * (size_t)HW, accA.x);
        __stcs(oc + 1 * (size_t)HW, accA.y);
        __stcs(oc + 2 * (size_t)HW, accA.z);
        __stcs(oc + 3 * (size_t)HW, accA.w);
        __stcs(oc + 4 * (size_t)HW, accB.x);
        __stcs(oc + 5 * (size_t)HW, accB.y);
        __stcs(oc + 6 * (size_t)HW, accB.z);
        __stcs(oc + 7 * (size_t)HW, accB.w);
    }
}

// ------------------------------------------------- trailing count reset
// Restores the d_count==0 invariant for the NEXT kernel_launch call.
__global__ void __launch_bounds__(256)
reset_kernel() {
    int z = blockIdx.x * 256 + threadIdx.x;     // 0 .. NPIX/4-1
    ((int4*)d_count)[z] = make_int4(0, 0, 0, 0);
}

extern "C" void kernel_launch(void* const* d_in, const int* in_sizes, int n_in,
                              void* d_out, int out_size) {
    const float* pts = (const float*)d_in[0];   // [B, P, 3]
    const float* src = (const float*)d_in[1];   // [B, C, P]
    float* out = (float*)d_out;                 // [B, C, H, W]

    prep_kernel<<<T_TILES + B_BLOCKS, 256>>>(src, pts);

    dim3 ggrid(NPIX / 256, 2);                  // (3344, 2)
    gather_kernel<<<ggrid, 256>>>(out);

    reset_kernel<<<R_BLOCKS, 256>>>();
}

// round 12
// speedup vs baseline: 2.2524x; 2.2524x over previous
#include <cuda_runtime.h>
#include <stdint.h>

// Fixed-shape problem constants
#define HH 352
#define WW 1216
#define PP 65536
#define CC 64
#define BB 2
#define HW (HH * WW)            // 428032
#define NPIX (BB * HW)          // 856064
#define MAXC 8                  // per-pixel candidate capacity (= reference K)

// Scratch (__device__ globals: allocation-free)
__device__ int    d_count[NPIX];
__device__ uint2  d_cand[NPIX * MAXC];          // {pid, bitcast(weight)}
__device__ float  d_featsT[BB * PP * CC];       // src transposed to [B*P, C]

#define T_TILES (PP / 32 * (CC / 32) * BB)      // 8192 transpose tiles
#define Z_BLOCKS (NPIX / 4 / 256)               // 836 zero blocks (exact)

// ------------------------------------------------- transpose + zero counts (fused)
__global__ void __launch_bounds__(256)
prep_kernel(const float* __restrict__ src) {
    int bid = blockIdx.x;
    int tid = threadIdx.x;

    if (bid < T_TILES) {
        // src [B, C, P] -> d_featsT [B*P, C], 32x32 smem tile
        __shared__ float tile[32][33];
        int pb   = bid & (PP / 32 - 1);
        int rest = bid >> 11;
        int cb   = rest & 1;
        int b    = rest >> 1;
        int tx = tid & 31, ty = tid >> 5;
        int pbase = pb * 32, cbase = cb * 32;
        const float* sb = src + (size_t)b * CC * PP;
        #pragma unroll
        for (int j = 0; j < 4; j++) {
            int c = cbase + ty + j * 8;
            tile[ty + j * 8][tx] = sb[(size_t)c * PP + pbase + tx];
        }
        __syncthreads();
        float* ob = d_featsT + ((size_t)b * PP) * CC;
        #pragma unroll
        for (int j = 0; j < 4; j++) {
            int p = pbase + ty + j * 8;
            ob[(size_t)p * CC + cbase + tx] = tile[tx][ty + j * 8];
        }
    } else {
        int z = (bid - T_TILES) * 256 + tid;    // 0 .. NPIX/4-1
        ((int4*)d_count)[z] = make_int4(0, 0, 0, 0);
    }
}

// ------------------------------------------------- build candidate lists
// r = 3/1216 NDC. Row pitch 2/352 > 2r -> only row i0 qualifies.
// Col pitch 2/1216, 2r spans <=3 centers -> only j0-1..j0+1.
__global__ void __launch_bounds__(256)
build_kernel(const float* __restrict__ pts) {
    int t = blockIdx.x * blockDim.x + threadIdx.x;
    if (t >= BB * PP) return;
    int b = t >> 16;

    float x = pts[3 * t + 0];
    float y = pts[3 * t + 1];
    float z = pts[3 * t + 2];

    const float r2     = (3.0f / 1216.0f) * (3.0f / 1216.0f);
    const float inv_r2 = 1216.0f * 1216.0f / 9.0f;

    int i0 = (int)floorf((y + 1.0f) * 0.5f * (float)HH);
    int j0 = (int)floorf((x + 1.0f) * 0.5f * (float)WW);

    if (!(z > 0.0f) || i0 < 0 || i0 >= HH) return;

    float yc  = ((float)i0 + 0.5f) * (2.0f / (float)HH) - 1.0f;
    float fy2 = (y - yc) * (y - yc);

    #pragma unroll
    for (int dxi = -1; dxi <= 1; dxi++) {
        int jj = j0 + dxi;
        if (jj < 0 || jj >= WW) continue;
        float xc = ((float)jj + 0.5f) * (2.0f / (float)WW) - 1.0f;
        float fx = x - xc;
        float d2 = fx * fx + fy2;
        if (d2 < r2) {
            float alpha = 1.0f - sqrtf(fmaxf(d2 * inv_r2, 0.001f));
            int pix = (b * HH + i0) * WW + jj;
            int idx = atomicAdd(&d_count[pix], 1);
            if (idx < MAXC)
                d_cand[pix * MAXC + idx] = make_uint2((unsigned)t, __float_as_uint(alpha));
        }
    }
}

// ------------------------------------------------- gather
// Thread = one pixel x 32 channels (blockIdx.y picks the half).
// Candidate list hoisted once; 4 channel-group passes + streaming stores.
// 6 blocks/SM (42-reg budget) -- 8 blocks/SM spills (R11 lesson).
__global__ void __launch_bounds__(256, 6)
gather_kernel(float* __restrict__ out) {
    int pix  = blockIdx.x * 256 + threadIdx.x;
    int half = blockIdx.y;                       // 0 or 1

    int n = d_count[pix];
    n = n < MAXC ? n : MAXC;

    // Hoist candidate entries into registers.
    const uint4* cb4 = (const uint4*)(d_cand + (size_t)pix * MAXC);
    uint4 e01 = make_uint4(0,0,0,0), e23 = e01, e45 = e01, e67 = e01;
    if (n > 0) e01 = __ldg(&cb4[0]);
    if (n > 2) e23 = __ldg(&cb4[1]);
    if (n > 4) e45 = __ldg(&cb4[2]);
    if (n > 6) e67 = __ldg(&cb4[3]);

    unsigned pid[MAXC];
    float    wgt[MAXC];
    pid[0] = e01.x; wgt[0] = __uint_as_float(e01.y);
    pid[1] = e01.z; wgt[1] = __uint_as_float(e01.w);
    pid[2] = e23.x; wgt[2] = __uint_as_float(e23.y);
    pid[3] = e23.z; wgt[3] = __uint_as_float(e23.w);
    pid[4] = e45.x; wgt[4] = __uint_as_float(e45.y);
    pid[5] = e45.z; wgt[5] = __uint_as_float(e45.w);
    pid[6] = e67.x; wgt[6] = __uint_as_float(e67.y);
    pid[7] = e67.z; wgt[7] = __uint_as_float(e67.w);

    int b   = pix / HW;
    int loc = pix - b * HW;
    float* ob = out + (size_t)b * CC * HW + (size_t)(half * 32) * HW + loc;

    #pragma unroll
    for (int g = 0; g < 4; g++) {
        float4 accA = make_float4(0.f, 0.f, 0.f, 0.f);
        float4 accB = make_float4(0.f, 0.f, 0.f, 0.f);
        #pragma unroll
        for (int i = 0; i < MAXC; i++) {
            if (i < n) {
                const float4* fp = (const float4*)
                    (d_featsT + (size_t)pid[i] * CC + half * 32 + g * 8);
                float4 a = __ldg(fp);
                float4 c = __ldg(fp + 1);
                float w = wgt[i];
                accA.x += w * a.x; accA.y += w * a.y; accA.z += w * a.z; accA.w += w * a.w;
                accB.x += w * c.x; accB.y += w * c.y; accB.z += w * c.z; accB.w += w * c.w;
            }
        }
        float* oc = ob + (size_t)(g * 8) * HW;
        __stcs(oc + 0 * (size_t)HW, accA.x);
        __stcs(oc + 1 * (size_t)HW, accA.y);
        __stcs(oc + 2 * (size_t)HW, accA.z);
        __stcs(oc + 3 * (size_t)HW, accA.w);
        __stcs(oc + 4 * (size_t)HW, accB.x);
        __stcs(oc + 5 * (size_t)HW, accB.y);
        __stcs(oc + 6 * (size_t)HW, accB.z);
        __stcs(oc + 7 * (size_t)HW, accB.w);
    }
}

extern "C" void kernel_launch(void* const* d_in, const int* in_sizes, int n_in,
                              void* d_out, int out_size) {
    const float* pts = (const float*)d_in[0];   // [B, P, 3]
    const float* src = (const float*)d_in[1];   // [B, C, P]
    float* out = (float*)d_out;                 // [B, C, H, W]

    prep_kernel<<<T_TILES + Z_BLOCKS, 256>>>(src);
    build_kernel<<<(BB * PP) / 256, 256>>>(pts);

    dim3 ggrid(NPIX / 256, 2);                  // (3344, 2)
    gather_kernel<<<ggrid, 256>>>(out);
}

// round 13
// speedup vs baseline: 2.6088x; 1.1582x over previous
#include <cuda_runtime.h>
#include <stdint.h>

// Fixed-shape problem constants
#define HH 352
#define WW 1216
#define PP 65536
#define CC 64
#define BB 2
#define HW (HH * WW)            // 428032
#define NPIX (BB * HW)          // 856064
#define MAXC 8                  // per-pixel candidate capacity (= reference K)

// Scratch (__device__ globals: allocation-free).
// INVARIANT: d_count == 0 at entry of every kernel_launch call.
//  - first call: BSS zero-initialization
//  - later calls: trailing reset_kernel of the previous call
// Every call performs identical work -> graph-replay deterministic.
__device__ int    d_count[NPIX];
__device__ uint2  d_cand[NPIX * MAXC];          // {pid, bitcast(weight)}
__device__ float  d_featsT[BB * PP * CC];       // src transposed to [B*P, C]

#define T_TILES (PP / 32 * (CC / 32) * BB)      // 8192 transpose tiles
#define B_BLOCKS ((BB * PP) / 256)              // 512 build blocks
#define R_BLOCKS (NPIX / 4 / 256)               // 836 reset blocks

// ------------------------------------------------- transpose + build (fused)
// Disjoint data: transpose src->featsT; build pts->count/cand (counts are
// pre-zeroed by the invariant). Blocks run concurrently in one grid.
__global__ void __launch_bounds__(256)
prep_kernel(const float* __restrict__ src, const float* __restrict__ pts) {
    int bid = blockIdx.x;
    int tid = threadIdx.x;

    if (bid < T_TILES) {
        // src [B, C, P] -> d_featsT [B*P, C], 32x32 smem tile
        __shared__ float tile[32][33];
        int pb   = bid & (PP / 32 - 1);
        int rest = bid >> 11;
        int cb   = rest & 1;
        int b    = rest >> 1;
        int tx = tid & 31, ty = tid >> 5;
        int pbase = pb * 32, cbase = cb * 32;
        const float* sb = src + (size_t)b * CC * PP;
        #pragma unroll
        for (int j = 0; j < 4; j++) {
            int c = cbase + ty + j * 8;
            tile[ty + j * 8][tx] = sb[(size_t)c * PP + pbase + tx];
        }
        __syncthreads();
        float* ob = d_featsT + ((size_t)b * PP) * CC;
        #pragma unroll
        for (int j = 0; j < 4; j++) {
            int p = pbase + ty + j * 8;
            ob[(size_t)p * CC + cbase + tx] = tile[tx][ty + j * 8];
        }
    } else {
        // ---- build candidate lists ----
        // r = 3/1216 NDC. Row pitch 2/352 > 2r -> only row i0 qualifies.
        // Col pitch 2/1216, 2r spans <=3 centers -> only j0-1..j0+1.
        int t = (bid - T_TILES) * 256 + tid;    // point index
        int b = t >> 16;

        float x = pts[3 * t + 0];
        float y = pts[3 * t + 1];
        float z = pts[3 * t + 2];

        const float r2     = (3.0f / 1216.0f) * (3.0f / 1216.0f);
        const float inv_r2 = 1216.0f * 1216.0f / 9.0f;

        int i0 = (int)floorf((y + 1.0f) * 0.5f * (float)HH);
        int j0 = (int)floorf((x + 1.0f) * 0.5f * (float)WW);

        if (!(z > 0.0f) || i0 < 0 || i0 >= HH) return;

        float yc  = ((float)i0 + 0.5f) * (2.0f / (float)HH) - 1.0f;
        float fy2 = (y - yc) * (y - yc);

        #pragma unroll
        for (int dxi = -1; dxi <= 1; dxi++) {
            int jj = j0 + dxi;
            if (jj < 0 || jj >= WW) continue;
            float xc = ((float)jj + 0.5f) * (2.0f / (float)WW) - 1.0f;
            float fx = x - xc;
            float d2 = fx * fx + fy2;
            if (d2 < r2) {
                float alpha = 1.0f - sqrtf(fmaxf(d2 * inv_r2, 0.001f));
                int pix = (b * HH + i0) * WW + jj;
                int idx = atomicAdd(&d_count[pix], 1);
                if (idx < MAXC)
                    d_cand[pix * MAXC + idx] = make_uint2((unsigned)t, __float_as_uint(alpha));
            }
        }
    }
}

// ------------------------------------------------- gather (exact R10 form)
// Thread = one pixel, ALL 64 channels. Candidate list read once into
// registers; 8 channel-group passes of accumulate + streaming stores.
// 6 blocks/SM (42-reg budget) -- 8 blocks/SM spills (R11 lesson).
__global__ void __launch_bounds__(256, 6)
gather_kernel(float* __restrict__ out) {
    int pix = blockIdx.x * 256 + threadIdx.x;

    int n = d_count[pix];
    n = n < MAXC ? n : MAXC;

    // Hoist candidate entries into registers.
    const uint4* cb4 = (const uint4*)(d_cand + (size_t)pix * MAXC);
    uint4 e01 = make_uint4(0,0,0,0), e23 = e01, e45 = e01, e67 = e01;
    if (n > 0) e01 = __ldg(&cb4[0]);
    if (n > 2) e23 = __ldg(&cb4[1]);
    if (n > 4) e45 = __ldg(&cb4[2]);
    if (n > 6) e67 = __ldg(&cb4[3]);

    unsigned pid[MAXC];
    float    wgt[MAXC];
    pid[0] = e01.x; wgt[0] = __uint_as_float(e01.y);
    pid[1] = e01.z; wgt[1] = __uint_as_float(e01.w);
    pid[2] = e23.x; wgt[2] = __uint_as_float(e23.y);
    pid[3] = e23.z; wgt[3] = __uint_as_float(e23.w);
    pid[4] = e45.x; wgt[4] = __uint_as_float(e45.y);
    pid[5] = e45.z; wgt[5] = __uint_as_float(e45.w);
    pid[6] = e67.x; wgt[6] = __uint_as_float(e67.y);
    pid[7] = e67.z; wgt[7] = __uint_as_float(e67.w);

    int b   = pix / HW;
    int loc = pix - b * HW;
    float* ob = out + (size_t)b * CC * HW + loc;

    #pragma unroll
    for (int g = 0; g < 8; g++) {
        float4 accA = make_float4(0.f, 0.f, 0.f, 0.f);
        float4 accB = make_float4(0.f, 0.f, 0.f, 0.f);
        #pragma unroll
        for (int i = 0; i < MAXC; i++) {
            if (i < n) {
                const float4* fp = (const float4*)(d_featsT + (size_t)pid[i] * CC + g * 8);
                float4 a = __ldg(fp);
                float4 c = __ldg(fp + 1);
                float w = wgt[i];
                accA.x += w * a.x; accA.y += w * a.y; accA.z += w * a.z; accA.w += w * a.w;
                accB.x += w * c.x; accB.y += w * c.y; accB.z += w * c.z; accB.w += w * c.w;
            }
        }
        float* oc = ob + (size_t)(g * 8) * HW;
        __stcs(oc + 0 * (size_t)HW, accA.x);
        __stcs(oc + 1 * (size_t)HW, accA.y);
        __stcs(oc + 2 * (size_t)HW, accA.z);
        __stcs(oc + 3 * (size_t)HW, accA.w);
        __stcs(oc + 4 * (size_t)HW, accB.x);
        __stcs(oc + 5 * (size_t)HW, accB.y);
        __stcs(oc + 6 * (size_t)HW, accB.z);
        __stcs(oc + 7 * (size_t)HW, accB.w);
    }
}

// ------------------------------------------------- trailing count reset
// Restores the d_count==0 invariant for the NEXT kernel_launch call.
__global__ void __launch_bounds__(256)
reset_kernel() {
    int z = blockIdx.x * 256 + threadIdx.x;     // 0 .. NPIX/4-1
    ((int4*)d_count)[z] = make_int4(0, 0, 0, 0);
}

extern "C" void kernel_launch(void* const* d_in, const int* in_sizes, int n_in,
                              void* d_out, int out_size) {
    const float* pts = (const float*)d_in[0];   // [B, P, 3]
    const float* src = (const float*)d_in[1];   // [B, C, P]
    float* out = (float*)d_out;                 // [B, C, H, W]

    prep_kernel<<<T_TILES + B_BLOCKS, 256>>>(src, pts);
    gather_kernel<<<NPIX / 256, 256>>>(out);    // 3344 blocks
    reset_kernel<<<R_BLOCKS, 256>>>();
}

// round 14
// speedup vs baseline: 2.7118x; 1.0395x over previous
#include <cuda_runtime.h>
#include <stdint.h>

// Fixed-shape problem constants
#define HH 352
#define WW 1216
#define PP 65536
#define CC 64
#define BB 2
#define HW (HH * WW)            // 428032
#define NPIX (BB * HW)          // 856064
#define MAXC 8                  // per-pixel candidate capacity (= reference K)

// Scratch (__device__ globals: allocation-free).
// INVARIANT: d_count == 0 at entry of every kernel_launch call.
//  - first call: BSS zero-initialization
//  - later calls: trailing reset_kernel of the previous call
__device__ int    d_count[NPIX];
__device__ uint2  d_cand[NPIX * MAXC];          // {pid, bitcast(weight)}
__device__ float  d_featsT[BB * PP * CC];       // src transposed to [B*P, C]

#define T_TILES ((PP / 128) * (CC / 32) * BB)   // 2048 transpose blocks (4 tiles each)
#define B_BLOCKS ((BB * PP) / 256)              // 512 build blocks
#define R_BLOCKS (NPIX / 4 / 256)               // 836 reset blocks

// ------------------------------------------------- transpose + build (fused)
// Transpose: each block handles a 32-channel x 128-point span as FOUR 32x32
// smem tiles; all 16 global loads issue before one sync (4x MLP vs 32x32).
__global__ void __launch_bounds__(256)
prep_kernel(const float* __restrict__ src, const float* __restrict__ pts) {
    int bid = blockIdx.x;
    int tid = threadIdx.x;

    if (bid < T_TILES) {
        __shared__ float tile[4][32][33];       // 16.9KB, stride-33 conflict-free
        int pb   = bid & (PP / 128 - 1);        // 512 point-spans
        int rest = bid >> 9;
        int cb   = rest & 1;
        int b    = rest >> 1;
        int tx = tid & 31, ty = tid >> 5;
        int pbase = pb * 128, cbase = cb * 32;
        const float* sb = src + (size_t)b * CC * PP;

        #pragma unroll
        for (int tt = 0; tt < 4; tt++) {
            #pragma unroll
            for (int j = 0; j < 4; j++) {
                int c = cbase + ty + j * 8;
                tile[tt][ty + j * 8][tx] = sb[(size_t)c * PP + pbase + tt * 32 + tx];
            }
        }
        __syncthreads();
        float* ob = d_featsT + ((size_t)b * PP) * CC;
        #pragma unroll
        for (int tt = 0; tt < 4; tt++) {
            #pragma unroll
            for (int j = 0; j < 4; j++) {
                int p = pbase + tt * 32 + ty + j * 8;
                ob[(size_t)p * CC + cbase + tx] = tile[tt][tx][ty + j * 8];
            }
        }
    } else {
        // ---- build candidate lists ----
        // r = 3/1216 NDC. Row pitch 2/352 > 2r -> only row i0 qualifies.
        // Col pitch 2/1216, 2r spans <=3 centers -> only j0-1..j0+1.
        int t = (bid - T_TILES) * 256 + tid;    // point index
        int b = t >> 16;

        float x = pts[3 * t + 0];
        float y = pts[3 * t + 1];
        float z = pts[3 * t + 2];

        const float r2     = (3.0f / 1216.0f) * (3.0f / 1216.0f);
        const float inv_r2 = 1216.0f * 1216.0f / 9.0f;

        int i0 = (int)floorf((y + 1.0f) * 0.5f * (float)HH);
        int j0 = (int)floorf((x + 1.0f) * 0.5f * (float)WW);

        if (!(z > 0.0f) || i0 < 0 || i0 >= HH) return;

        float yc  = ((float)i0 + 0.5f) * (2.0f / (float)HH) - 1.0f;
        float fy2 = (y - yc) * (y - yc);

        #pragma unroll
        for (int dxi = -1; dxi <= 1; dxi++) {
            int jj = j0 + dxi;
            if (jj < 0 || jj >= WW) continue;
            float xc = ((float)jj + 0.5f) * (2.0f / (float)WW) - 1.0f;
            float fx = x - xc;
            float d2 = fx * fx + fy2;
            if (d2 < r2) {
                float alpha = 1.0f - sqrtf(fmaxf(d2 * inv_r2, 0.001f));
                int pix = (b * HH + i0) * WW + jj;
                int idx = atomicAdd(&d_count[pix], 1);
                if (idx < MAXC)
                    d_cand[pix * MAXC + idx] = make_uint2((unsigned)t, __float_as_uint(alpha));
            }
        }
    }
}

// ------------------------------------------------- gather (proven R10 form)
// Thread = one pixel, ALL 64 channels. Candidate list read once into
// registers; 8 channel-group passes of accumulate + streaming stores.
// 6 blocks/SM (42-reg budget) -- 8 blocks/SM spills (R11 lesson).
__global__ void __launch_bounds__(256, 6)
gather_kernel(float* __restrict__ out) {
    int pix = blockIdx.x * 256 + threadIdx.x;

    int n = d_count[pix];
    n = n < MAXC ? n : MAXC;

    const uint4* cb4 = (const uint4*)(d_cand + (size_t)pix * MAXC);
    uint4 e01 = make_uint4(0,0,0,0), e23 = e01, e45 = e01, e67 = e01;
    if (n > 0) e01 = __ldg(&cb4[0]);
    if (n > 2) e23 = __ldg(&cb4[1]);
    if (n > 4) e45 = __ldg(&cb4[2]);
    if (n > 6) e67 = __ldg(&cb4[3]);

    unsigned pid[MAXC];
    float    wgt[MAXC];
    pid[0] = e01.x; wgt[0] = __uint_as_float(e01.y);
    pid[1] = e01.z; wgt[1] = __uint_as_float(e01.w);
    pid[2] = e23.x; wgt[2] = __uint_as_float(e23.y);
    pid[3] = e23.z; wgt[3] = __uint_as_float(e23.w);
    pid[4] = e45.x; wgt[4] = __uint_as_float(e45.y);
    pid[5] = e45.z; wgt[5] = __uint_as_float(e45.w);
    pid[6] = e67.x; wgt[6] = __uint_as_float(e67.y);
    pid[7] = e67.z; wgt[7] = __uint_as_float(e67.w);

    int b   = pix / HW;
    int loc = pix - b * HW;
    float* ob = out + (size_t)b * CC * HW + loc;

    #pragma unroll
    for (int g = 0; g < 8; g++) {
        float4 accA = make_float4(0.f, 0.f, 0.f, 0.f);
        float4 accB = make_float4(0.f, 0.f, 0.f, 0.f);
        #pragma unroll
        for (int i = 0; i < MAXC; i++) {
            if (i < n) {
                const float4* fp = (const float4*)(d_featsT + (size_t)pid[i] * CC + g * 8);
                float4 a = __ldg(fp);
                float4 c = __ldg(fp + 1);
                float w = wgt[i];
                accA.x += w * a.x; accA.y += w * a.y; accA.z += w * a.z; accA.w += w * a.w;
                accB.x += w * c.x; accB.y += w * c.y; accB.z += w * c.z; accB.w += w * c.w;
            }
        }
        float* oc = ob + (size_t)(g * 8) * HW;
        __stcs(oc + 0 * (size_t)HW, accA.x);
        __stcs(oc + 1 * (size_t)HW, accA.y);
        __stcs(oc + 2 * (size_t)HW, accA.z);
        __stcs(oc + 3 * (size_t)HW, accA.w);
        __stcs(oc + 4 * (size_t)HW, accB.x);
        __stcs(oc + 5 * (size_t)HW, accB.y);
        __stcs(oc + 6 * (size_t)HW, accB.z);
        __stcs(oc + 7 * (size_t)HW, accB.w);
    }
}

// ------------------------------------------------- trailing count reset
__global__ void __launch_bounds__(256)
reset_kernel() {
    int z = blockIdx.x * 256 + threadIdx.x;     // 0 .. NPIX/4-1
    ((int4*)d_count)[z] = make_int4(0, 0, 0, 0);
}

extern "C" void kernel_launch(void* const* d_in, const int* in_sizes, int n_in,
                              void* d_out, int out_size) {
    const float* pts = (const float*)d_in[0];   // [B, P, 3]
    const float* src = (const float*)d_in[1];   // [B, C, P]
    float* out = (float*)d_out;                 // [B, C, H, W]

    prep_kernel<<<T_TILES + B_BLOCKS, 256>>>(src, pts);
    gather_kernel<<<NPIX / 256, 256>>>(out);    // 3344 blocks
    reset_kernel<<<R_BLOCKS, 256>>>();
}